// round 12
// baseline (speedup 1.0000x reference)
#include <cuda_runtime.h>
#include <cstddef>

#define B_  32
#define N_  128
#define D_  512
#define H_  512
#define T_  31
#define TQ  32
#define G4  2048   // 4*H
#define FEATW 1024 // attn|hop feature cols
#define NLSTM 128  // LSTM blocks in merged kernel
#define NGEMM (16 * 64) // feat tiles: 1024x1024? -> (FEATW/64) x (4096/64) = 16 x 64

// ---------------- device scratch ----------------
__device__ float g_feat [B_*N_*FEATW];    // [B*N][1024]: cols 0..511 attn, 512..1023 hop
__device__ float g_wfeat[D_*FEATW];       // [k][1024] = attn_wm | hop_wm
__device__ float g_wiht[D_*G4];           // packed: [k][j*4+g] = w_ih[g*H+j][k]
__device__ float g_whh [H_*G4];           // packed: [k][j*4+g] = w_hh[g*H+j][k]
__device__ float g_bias[G4];              // packed b_ih+b_hh
__device__ float g_X   [B_*TQ*D_];        // lstm input incl. init_i row
__device__ float g_xg  [B_*TQ*G4];        // X @ w_ih^T + bias (packed cols)
__device__ float g_hT  [2][H_*B_];        // transposed h state: [k][b]
__device__ float g_cbufp[B_*H_];          // (unused placeholder)
__device__ float g_query [B_*TQ*H_];
__device__ float g_qw    [B_*TQ*H_];
__device__ float g_score [B_*TQ*N_];
__device__ float g_query2[B_*TQ*H_];
__device__ float g_qw2   [B_*TQ*H_];
__device__ unsigned g_bar;

__device__ __forceinline__ float tanh_fast(float x) {
    float y; asm("tanh.approx.f32 %0, %1;" : "=f"(y) : "f"(x)); return y;
}
__device__ __forceinline__ float sigmoid_f(float x) {
    return 1.f / (1.f + __expf(-x));
}

// ---------------- weight pack / transpose (R3, passed) ----------------
__global__ void pack_kernel(const float* __restrict__ w_ih, const float* __restrict__ w_hh,
                            const float* __restrict__ b_ih, const float* __restrict__ b_hh,
                            const float* __restrict__ attn_wm, const float* __restrict__ hop_wm) {
    int idx = blockIdx.x * blockDim.x + threadIdx.x;
    if (idx < D_ * G4) {
        int k = idx >> 11, col = idx & 2047;
        int j = col >> 2, g = col & 3;
        int row = g * H_ + j;
        g_wiht[idx] = w_ih[row * D_ + k];
        g_whh [idx] = w_hh[row * H_ + k];
        if (idx < G4) g_bias[idx] = b_ih[row] + b_hh[row];
    }
    if (idx < D_ * FEATW) {
        int k = idx >> 10, c = idx & 1023;
        g_wfeat[idx] = (c < 512) ? attn_wm[k * H_ + c] : hop_wm[k * H_ + (c - 512)];
    }
}

__global__ void build_x_kernel(const float* __restrict__ lstm_in, const float* __restrict__ init_i) {
    int idx = blockIdx.x * blockDim.x + threadIdx.x;
    if (idx >= B_ * TQ * D_) return;
    int d  = idx & (D_ - 1);
    int bt = idx >> 9;
    int t = bt & 31, b = bt >> 5;
    g_X[idx] = (t == 0) ? init_i[d] : lstm_in[(b * T_ + (t - 1)) * D_ + d];
}

__global__ void init_h_kernel(const float* __restrict__ init_h) {
    int idx = blockIdx.x * blockDim.x + threadIdx.x;
    if (idx == 0) g_bar = 0u;
    if (idx >= B_ * H_) return;
    int j = idx >> 5;                     // idx = j*32 + b
    g_hT[0][idx] = init_h[j];
}

// ---------------- sgemm64 body (R1-proven numerics), shared by wrapper + merged ----------------
__device__ __forceinline__ void sgemm64_body(
    const float* __restrict__ A, const float* __restrict__ Bm,
    float* __restrict__ C, const float* __restrict__ bias,
    int M, int N, int K, int bx, int by,
    float* As_, float* Bs_)   // As_[16*64], Bs_[16*64]
{
    float (*As)[64] = (float(*)[64])As_;
    float (*Bs)[64] = (float(*)[64])Bs_;
    const int bm = by * 64, bn = bx * 64;
    const int tid = threadIdx.x;
    const int tn = tid & 15, tm = tid >> 4;
    const int arow = tid >> 2,  acol = (tid & 3) << 2;
    const int brow = tid >> 4,  bcol = (tid & 15) << 2;
    float acc[4][4] = {};
    for (int k0 = 0; k0 < K; k0 += 16) {
        float4 a4 = *(const float4*)(A  + (size_t)(bm + arow) * K + k0 + acol);
        float4 b4 = *(const float4*)(Bm + (size_t)(k0 + brow) * N + bn + bcol);
        As[acol + 0][arow] = a4.x;
        As[acol + 1][arow] = a4.y;
        As[acol + 2][arow] = a4.z;
        As[acol + 3][arow] = a4.w;
        *(float4*)&Bs[brow][bcol] = b4;
        __syncthreads();
#pragma unroll
        for (int k = 0; k < 16; k++) {
            float4 av = *(const float4*)&As[k][tm << 2];
            float4 bv = *(const float4*)&Bs[k][tn << 2];
            float a_[4] = {av.x, av.y, av.z, av.w};
            float b_[4] = {bv.x, bv.y, bv.z, bv.w};
#pragma unroll
            for (int i = 0; i < 4; i++)
#pragma unroll
                for (int j = 0; j < 4; j++) acc[i][j] += a_[i] * b_[j];
        }
        __syncthreads();
    }
#pragma unroll
    for (int i = 0; i < 4; i++) {
        int row = bm + (tm << 2) + i;
#pragma unroll
        for (int j = 0; j < 4; j++) {
            int col = bn + (tn << 2) + j;
            float v = acc[i][j];
            if (bias) v += bias[col];
            C[(size_t)row * N + col] = v;
        }
    }
}

__global__ void sgemm64(const float* __restrict__ A, const float* __restrict__ Bm,
                        float* __restrict__ C, const float* __restrict__ bias,
                        int M, int N, int K) {
    __shared__ __align__(16) float As[16 * 64];
    __shared__ __align__(16) float Bs[16 * 64];
    sgemm64_body(A, Bm, C, bias, M, N, K, blockIdx.x, blockIdx.y, As, Bs);
}

// ---------------- LSTM body (R4-proven persistent recurrence) ----------------
__device__ void lstm_body(const float* __restrict__ init_c, int bid, float* ws) {
    __shared__ float red[8][32 * 17 + 1];    // [ks][b*17 + c]
    __shared__ float cst[128];               // c state: [b*4 + jl]
    const int tid = threadIdx.x;
    const int ks = tid >> 5, lane = tid & 31;
    const int bq = lane & 7, cq = lane >> 3;

    {
        const float* src = g_whh + bid * 16;
        for (int i = tid; i < 512 * 4; i += 256) {   // 2048 float4s
            int k = i >> 2, cc = (i & 3) << 2;
            *(float4*)&ws[k * 16 + cc] = *(const float4*)(src + (size_t)k * G4 + cc);
        }
    }
    if (tid < 128) cst[tid] = init_c[bid * 4 + (tid & 3)];
    __syncthreads();

    const float* __restrict__ wp = ws + (ks << 6) * 16 + (cq << 2);

    for (int t = 0; t < TQ; t++) {
        const float* __restrict__ hp = g_hT[t & 1] + (ks << 6) * B_ + (bq << 2);
        float acc[4][4] = {};
#pragma unroll 8
        for (int k = 0; k < 64; k++) {
            float4 h4 = *(const float4*)(hp + k * B_);
            float4 w4 = *(const float4*)(wp + k * 16);
            float h_[4] = {h4.x, h4.y, h4.z, h4.w};
            float w_[4] = {w4.x, w4.y, w4.z, w4.w};
#pragma unroll
            for (int i = 0; i < 4; i++)
#pragma unroll
                for (int j = 0; j < 4; j++) acc[i][j] += h_[i] * w_[j];
        }
#pragma unroll
        for (int i = 0; i < 4; i++)
#pragma unroll
            for (int j = 0; j < 4; j++)
                red[ks][((bq << 2) + i) * 17 + (cq << 2) + j] = acc[i][j];
        __syncthreads();

        if (tid < 128) {
            int b = tid >> 2, jl = tid & 3;
            int j = (bid << 2) + jl;
            int bt = b * TQ + t;
            const float* xg = g_xg + (size_t)bt * G4 + bid * 16 + (jl << 2);
            float gate[4];
#pragma unroll
            for (int g = 0; g < 4; g++) {
                int c = (jl << 2) + g;
                float s = 0.f;
#pragma unroll
                for (int kk = 0; kk < 8; kk++) s += red[kk][b * 17 + c];
                gate[g] = s + xg[g];
            }
            float c_ = sigmoid_f(gate[1]) * cst[tid] + sigmoid_f(gate[0]) * tanhf(gate[2]);
            float h_ = sigmoid_f(gate[3]) * tanhf(c_);
            cst[tid] = c_;
            g_hT[(t & 1) ^ 1][j * B_ + b] = h_;
            g_query[(size_t)bt * H_ + j] = h_;
            __threadfence();
        }
        __syncthreads();                       // red WAR + all writers fenced
        if (t != TQ - 1) {
            if (tid == 0) {
                atomicAdd(&g_bar, 1u);
                volatile unsigned* p = &g_bar;
                unsigned target = (unsigned)NLSTM * (unsigned)(t + 1);
                while (*p < target) {}
                __threadfence();
            }
            __syncthreads();
        }
    }
}

// ---------------- merged kernel: LSTM (bid<128) + feature GEMM (bid>=128) ----------------
// LSTM blocks first -> co-resident in wave 1; GEMM blocks fill spare capacity,
// overlapping the feature GEMM with the latency-bound recurrence.
__global__ void __launch_bounds__(256) lstm_feat_kernel(
    const float* __restrict__ init_c,
    const float* __restrict__ attn_mem)
{
    extern __shared__ __align__(16) float dynsm[];   // 32 KB
    int bid = blockIdx.x;
    if (bid < NLSTM) {
        lstm_body(init_c, bid, dynsm);               // uses full 32 KB as w slice
    } else {
        int gid = bid - NLSTM;                       // 0..1023
        int bx = gid & 15, by = gid >> 4;            // FEATW/64=16 x 4096/64=64
        sgemm64_body(attn_mem, g_wfeat, g_feat, nullptr,
                     B_ * N_, FEATW, D_, bx, by, dynsm, dynsm + 16 * 64);
    }
}

// ---------------- attention score (R3, passed) ----------------
__global__ void score_kernel(const float* __restrict__ feat, int ST,
                             const float* __restrict__ qw,
                             const float* __restrict__ v, float* __restrict__ out) {
    __shared__ __align__(16) float q_s[H_];
    __shared__ __align__(16) float v_s[H_];
    int bt = blockIdx.x;                 // 1024 blocks
    int b  = bt >> 5;
    int tid = threadIdx.x;               // 256
    q_s[tid]       = qw[(size_t)bt * H_ + tid];
    q_s[tid + 256] = qw[(size_t)bt * H_ + tid + 256];
    v_s[tid]       = v[tid];
    v_s[tid + 256] = v[tid + 256];
    __syncthreads();
    int warp = tid >> 5, lane = tid & 31;
    const float* fb = feat + (size_t)(b * N_) * ST;
    for (int n = warp; n < N_; n += 8) {
        const float* fr = fb + (size_t)n * ST;
        float acc = 0.f;
#pragma unroll
        for (int c = 0; c < 4; c++) {
            int h = c * 128 + lane * 4;
            float4 f4 = *(const float4*)(fr + h);
            float4 q4 = *(const float4*)(q_s + h);
            float4 v4 = *(const float4*)(v_s + h);
            acc += tanh_fast(f4.x + q4.x) * v4.x;
            acc += tanh_fast(f4.y + q4.y) * v4.y;
            acc += tanh_fast(f4.z + q4.z) * v4.z;
            acc += tanh_fast(f4.w + q4.w) * v4.w;
        }
#pragma unroll
        for (int s = 16; s; s >>= 1) acc += __shfl_xor_sync(0xffffffffu, acc, s);
        if (lane == 0) out[(size_t)bt * N_ + n] = acc;
    }
}

// ---------------- masked softmax + weighted sum (R3, passed) ----------------
__global__ void softmax_wsum_kernel(const int* __restrict__ mem_sizes,
                                    const float* __restrict__ hopfeat, int ST) {
    __shared__ float p_s[N_];
    __shared__ float red[128];
    int bt = blockIdx.x, b = bt >> 5;
    int tid = threadIdx.x;               // 128
    int ms = mem_sizes[b];
    float s = g_score[bt * N_ + tid];
    s = (tid < ms) ? s : -1e30f;
    red[tid] = s; __syncthreads();
    for (int o = 64; o; o >>= 1) { if (tid < o) red[tid] = fmaxf(red[tid], red[tid + o]); __syncthreads(); }
    float mx = red[0]; __syncthreads();
    float e = __expf(s - mx);
    red[tid] = e; __syncthreads();
    for (int o = 64; o; o >>= 1) { if (tid < o) red[tid] += red[tid + o]; __syncthreads(); }
    float inv = 1.f / red[0];
    p_s[tid] = e * inv;
    __syncthreads();
    const float* fb = hopfeat + (size_t)(b * N_) * ST;
    int h = tid * 4;
    float4 acc = {0.f, 0.f, 0.f, 0.f};
#pragma unroll 4
    for (int n = 0; n < N_; n++) {
        float p = p_s[n];
        float4 f = *(const float4*)(fb + (size_t)n * ST + h);
        acc.x += p * f.x; acc.y += p * f.y; acc.z += p * f.z; acc.w += p * f.w;
    }
    *(float4*)&g_query2[(size_t)bt * H_ + h] = acc;
}

// ---------------- launch ----------------
static float* sym(const void* s) {
    void* p = nullptr;
    cudaGetSymbolAddress(&p, s);
    return (float*)p;
}

extern "C" void kernel_launch(void* const* d_in, const int* in_sizes, int n_in,
                              void* d_out, int out_size) {
    const float* attn_mem = (const float*)d_in[0];
    const int*   mem_sizes= (const int*)  d_in[1];
    const float* lstm_in  = (const float*)d_in[2];
    const float* init_h   = (const float*)d_in[3];
    const float* init_c   = (const float*)d_in[4];
    const float* init_i   = (const float*)d_in[5];
    const float* w_ih     = (const float*)d_in[6];
    const float* w_hh     = (const float*)d_in[7];
    const float* b_ih     = (const float*)d_in[8];
    const float* b_hh     = (const float*)d_in[9];
    const float* attn_wm  = (const float*)d_in[10];
    const float* attn_wq  = (const float*)d_in[11];
    const float* attn_v   = (const float*)d_in[12];
    const float* hop_wm   = (const float*)d_in[13];
    const float* hop_wq   = (const float*)d_in[14];
    const float* hop_v    = (const float*)d_in[15];
    float* out = (float*)d_out;

    float* p_feat   = sym(g_feat);
    float* p_wiht   = sym(g_wiht);
    float* p_bias   = sym(g_bias);
    float* p_X      = sym(g_X);
    float* p_xg     = sym(g_xg);
    float* p_query  = sym(g_query);
    float* p_qw     = sym(g_qw);
    float* p_score  = sym(g_score);
    float* p_query2 = sym(g_query2);
    float* p_qw2    = sym(g_qw2);

    cudaFuncSetAttribute(lstm_feat_kernel,
                         cudaFuncAttributeMaxDynamicSharedMemorySize, 512 * 16 * 4);

    // prep (packs feed everything below)
    pack_kernel   <<<(D_*G4 + 255)/256, 256>>>(w_ih, w_hh, b_ih, b_hh, attn_wm, hop_wm);
    build_x_kernel<<<(B_*TQ*D_ + 255)/256, 256>>>(lstm_in, init_i);
    init_h_kernel <<<(B_*H_ + 255)/256, 256>>>(init_h);

    // input gates first (LSTM depends on it): [1024,512] @ [512,2048] + bias
    sgemm64<<<dim3(G4/64, (B_*TQ)/64), 256>>>(p_X, p_wiht, p_xg, p_bias, B_*TQ, G4, D_);

    // merged: persistent LSTM (blocks 0-127) + feature GEMM (blocks 128-1151)
    lstm_feat_kernel<<<NLSTM + NGEMM, 256, 512*16*4>>>(init_c, attn_mem);

    // hop attention (hop feat = cols 512..1023 of g_feat)
    sgemm64<<<dim3(H_/64, (B_*TQ)/64), 256>>>(p_query, hop_wq, p_qw, nullptr, B_*TQ, H_, H_);
    score_kernel<<<B_*TQ, 256>>>(p_feat + 512, FEATW, p_qw, hop_v, p_score);
    softmax_wsum_kernel<<<B_*TQ, 128>>>(mem_sizes, p_feat + 512, FEATW);

    // final score (attn feat = cols 0..511)
    sgemm64<<<dim3(H_/64, (B_*TQ)/64), 256>>>(p_query2, attn_wq, p_qw2, nullptr, B_*TQ, H_, H_);
    score_kernel<<<B_*TQ, 256>>>(p_feat, FEATW, p_qw2, attn_v, out);
}

// round 13
// speedup vs baseline: 1.4147x; 1.4147x over previous
#include <cuda_runtime.h>
#include <cstddef>

#define B_  32
#define N_  128
#define D_  512
#define H_  512
#define T_  31
#define TQ  32
#define G4  2048   // 4*H
#define FEATW 1024 // attn|hop feature cols

// ---------------- device scratch ----------------
__device__ float g_feat [B_*N_*FEATW];    // [B*N][1024]: cols 0..511 attn, 512..1023 hop
__device__ float g_wfeat[D_*FEATW];       // [k][1024] = attn_wm | hop_wm
__device__ float g_wiht[D_*G4];           // packed: [k][j*4+g] = w_ih[g*H+j][k]
__device__ float g_whh [H_*G4];           // packed: [k][j*4+g] = w_hh[g*H+j][k]
__device__ float g_bias[G4];              // packed b_ih+b_hh
__device__ float g_X   [B_*TQ*D_];        // lstm input incl. init_i row
__device__ float g_xg  [B_*TQ*G4];        // X @ w_ih^T + bias (packed cols)
__device__ float g_hT  [2][H_*B_];        // transposed h state: [k][b], double-buffered
__device__ float g_query [B_*TQ*H_];
__device__ float g_qw    [B_*TQ*H_];
__device__ float g_score [B_*TQ*N_];
__device__ float g_query2[B_*TQ*H_];
__device__ float g_qw2   [B_*TQ*H_];
__device__ unsigned g_bar;

__device__ __forceinline__ float tanh_fast(float x) {
    float y; asm("tanh.approx.f32 %0, %1;" : "=f"(y) : "f"(x)); return y;
}
__device__ __forceinline__ float sigmoid_f(float x) {
    return 1.f / (1.f + __expf(-x));
}

// ---------------- weight pack / transpose (R3, passed) ----------------
__global__ void pack_kernel(const float* __restrict__ w_ih, const float* __restrict__ w_hh,
                            const float* __restrict__ b_ih, const float* __restrict__ b_hh,
                            const float* __restrict__ attn_wm, const float* __restrict__ hop_wm) {
    int idx = blockIdx.x * blockDim.x + threadIdx.x;
    if (idx < D_ * G4) {
        int k = idx >> 11, col = idx & 2047;
        int j = col >> 2, g = col & 3;
        int row = g * H_ + j;
        g_wiht[idx] = w_ih[row * D_ + k];
        g_whh [idx] = w_hh[row * H_ + k];
        if (idx < G4) g_bias[idx] = b_ih[row] + b_hh[row];
    }
    if (idx < D_ * FEATW) {
        int k = idx >> 10, c = idx & 1023;
        g_wfeat[idx] = (c < 512) ? attn_wm[k * H_ + c] : hop_wm[k * H_ + (c - 512)];
    }
}

__global__ void build_x_kernel(const float* __restrict__ lstm_in, const float* __restrict__ init_i) {
    int idx = blockIdx.x * blockDim.x + threadIdx.x;
    if (idx >= B_ * TQ * D_) return;
    int d  = idx & (D_ - 1);
    int bt = idx >> 9;
    int t = bt & 31, b = bt >> 5;
    g_X[idx] = (t == 0) ? init_i[d] : lstm_in[(b * T_ + (t - 1)) * D_ + d];
}

__global__ void init_h_kernel(const float* __restrict__ init_h) {
    int idx = blockIdx.x * blockDim.x + threadIdx.x;
    if (idx == 0) g_bar = 0u;
    if (idx >= B_ * H_) return;
    int j = idx >> 5;                     // idx = j*32 + b
    g_hT[0][idx] = init_h[j];
}

// ---------------- tiled fp32 GEMM 64x64 (R1-proven) ----------------
__global__ void sgemm64(const float* __restrict__ A, const float* __restrict__ Bm,
                        float* __restrict__ C, const float* __restrict__ bias,
                        int M, int N, int K) {
    __shared__ __align__(16) float As[16][64];   // [k][m]
    __shared__ __align__(16) float Bs[16][64];   // [k][n]
    const int bm = blockIdx.y * 64, bn = blockIdx.x * 64;
    const int tid = threadIdx.x;
    const int tn = tid & 15, tm = tid >> 4;
    const int arow = tid >> 2,  acol = (tid & 3) << 2;
    const int brow = tid >> 4,  bcol = (tid & 15) << 2;
    float acc[4][4] = {};
    for (int k0 = 0; k0 < K; k0 += 16) {
        float4 a4 = *(const float4*)(A  + (size_t)(bm + arow) * K + k0 + acol);
        float4 b4 = *(const float4*)(Bm + (size_t)(k0 + brow) * N + bn + bcol);
        As[acol + 0][arow] = a4.x;
        As[acol + 1][arow] = a4.y;
        As[acol + 2][arow] = a4.z;
        As[acol + 3][arow] = a4.w;
        *(float4*)&Bs[brow][bcol] = b4;
        __syncthreads();
#pragma unroll
        for (int k = 0; k < 16; k++) {
            float4 av = *(const float4*)&As[k][tm << 2];
            float4 bv = *(const float4*)&Bs[k][tn << 2];
            float a_[4] = {av.x, av.y, av.z, av.w};
            float b_[4] = {bv.x, bv.y, bv.z, bv.w};
#pragma unroll
            for (int i = 0; i < 4; i++)
#pragma unroll
                for (int j = 0; j < 4; j++) acc[i][j] += a_[i] * b_[j];
        }
        __syncthreads();
    }
#pragma unroll
    for (int i = 0; i < 4; i++) {
        int row = bm + (tm << 2) + i;
#pragma unroll
        for (int j = 0; j < 4; j++) {
            int col = bn + (tn << 2) + j;
            float v = acc[i][j];
            if (bias) v += bias[col];
            C[(size_t)row * N + col] = v;
        }
    }
}

// ---------------- persistent LSTM with L2-native release/acquire barrier ----------------
// 128 blocks (all co-resident), block owns 16 packed gate cols; w slice in smem.
// h state moves through L2 only (__stcg/__ldcg) -> NO L1 flushes, no threadfence.
// Arrive: bar.sync then tid0 red.release.gpu; depart: tid0 ld.acquire.gpu poll + bar.sync.
__global__ void __launch_bounds__(256, 1) lstm_persist_kernel(const float* __restrict__ init_c) {
    extern __shared__ float ws[];            // [512][16]  32KB dynamic
    __shared__ float red[8][32 * 17 + 1];    // [ks][b*17 + c]
    __shared__ float cst[128];               // c state: [b*4 + jl]
    const int bid = blockIdx.x;
    const int tid = threadIdx.x;
    const int ks = tid >> 5, lane = tid & 31;
    const int bq = lane & 7, cq = lane >> 3;

    {
        const float* src = g_whh + bid * 16;
        for (int i = tid; i < 512 * 4; i += 256) {   // 2048 float4s
            int k = i >> 2, cc = (i & 3) << 2;
            *(float4*)&ws[k * 16 + cc] = *(const float4*)(src + (size_t)k * G4 + cc);
        }
    }
    if (tid < 128) cst[tid] = init_c[bid * 4 + (tid & 3)];
    __syncthreads();

    const float* __restrict__ wp = ws + (ks << 6) * 16 + (cq << 2);

    for (int t = 0; t < TQ; t++) {
        const float* __restrict__ hp = g_hT[t & 1] + (ks << 6) * B_ + (bq << 2);
        float acc[4][4] = {};
#pragma unroll 8
        for (int k = 0; k < 64; k++) {
            float4 h4 = __ldcg((const float4*)(hp + k * B_));   // L2-coherent read
            float4 w4 = *(const float4*)(wp + k * 16);
            float h_[4] = {h4.x, h4.y, h4.z, h4.w};
            float w_[4] = {w4.x, w4.y, w4.z, w4.w};
#pragma unroll
            for (int i = 0; i < 4; i++)
#pragma unroll
                for (int j = 0; j < 4; j++) acc[i][j] += h_[i] * w_[j];
        }
#pragma unroll
        for (int i = 0; i < 4; i++)
#pragma unroll
            for (int j = 0; j < 4; j++)
                red[ks][((bq << 2) + i) * 17 + (cq << 2) + j] = acc[i][j];
        __syncthreads();

        if (tid < 128) {
            int b = tid >> 2, jl = tid & 3;
            int j = (bid << 2) + jl;
            int bt = b * TQ + t;
            const float* xg = g_xg + (size_t)bt * G4 + bid * 16 + (jl << 2);
            float gate[4];
#pragma unroll
            for (int g = 0; g < 4; g++) {
                int c = (jl << 2) + g;
                float s = 0.f;
#pragma unroll
                for (int kk = 0; kk < 8; kk++) s += red[kk][b * 17 + c];
                gate[g] = s + xg[g];
            }
            float c_ = sigmoid_f(gate[1]) * cst[tid] + sigmoid_f(gate[0]) * tanhf(gate[2]);
            float h_ = sigmoid_f(gate[3]) * tanhf(c_);
            cst[tid] = c_;
            __stcg(&g_hT[(t & 1) ^ 1][j * B_ + b], h_);         // L2-coherent write
            __stcg(&g_query[(size_t)bt * H_ + j], h_);
        }
        __syncthreads();                        // red WAR + orders h stores before release
        if (t != TQ - 1) {
            if (tid == 0) {
                asm volatile("red.release.gpu.global.add.u32 [%0], 1;"
                             :: "l"(&g_bar) : "memory");
                unsigned target = 128u * (unsigned)(t + 1);
                unsigned v;
                do {
                    asm volatile("ld.acquire.gpu.global.u32 %0, [%1];"
                                 : "=r"(v) : "l"(&g_bar) : "memory");
                } while (v < target);
            }
            __syncthreads();                    // broadcast acquire to all threads
        }
    }
}

// ---------------- attention score (R3, passed) ----------------
__global__ void score_kernel(const float* __restrict__ feat, int ST,
                             const float* __restrict__ qw,
                             const float* __restrict__ v, float* __restrict__ out) {
    __shared__ __align__(16) float q_s[H_];
    __shared__ __align__(16) float v_s[H_];
    int bt = blockIdx.x;                 // 1024 blocks
    int b  = bt >> 5;
    int tid = threadIdx.x;               // 256
    q_s[tid]       = qw[(size_t)bt * H_ + tid];
    q_s[tid + 256] = qw[(size_t)bt * H_ + tid + 256];
    v_s[tid]       = v[tid];
    v_s[tid + 256] = v[tid + 256];
    __syncthreads();
    int warp = tid >> 5, lane = tid & 31;
    const float* fb = feat + (size_t)(b * N_) * ST;
    for (int n = warp; n < N_; n += 8) {
        const float* fr = fb + (size_t)n * ST;
        float acc = 0.f;
#pragma unroll
        for (int c = 0; c < 4; c++) {
            int h = c * 128 + lane * 4;
            float4 f4 = *(const float4*)(fr + h);
            float4 q4 = *(const float4*)(q_s + h);
            float4 v4 = *(const float4*)(v_s + h);
            acc += tanh_fast(f4.x + q4.x) * v4.x;
            acc += tanh_fast(f4.y + q4.y) * v4.y;
            acc += tanh_fast(f4.z + q4.z) * v4.z;
            acc += tanh_fast(f4.w + q4.w) * v4.w;
        }
#pragma unroll
        for (int s = 16; s; s >>= 1) acc += __shfl_xor_sync(0xffffffffu, acc, s);
        if (lane == 0) out[(size_t)bt * N_ + n] = acc;
    }
}

// ---------------- masked softmax + weighted sum (R3, passed) ----------------
__global__ void softmax_wsum_kernel(const int* __restrict__ mem_sizes,
                                    const float* __restrict__ hopfeat, int ST) {
    __shared__ float p_s[N_];
    __shared__ float red[128];
    int bt = blockIdx.x, b = bt >> 5;
    int tid = threadIdx.x;               // 128
    int ms = mem_sizes[b];
    float s = g_score[bt * N_ + tid];
    s = (tid < ms) ? s : -1e30f;
    red[tid] = s; __syncthreads();
    for (int o = 64; o; o >>= 1) { if (tid < o) red[tid] = fmaxf(red[tid], red[tid + o]); __syncthreads(); }
    float mx = red[0]; __syncthreads();
    float e = __expf(s - mx);
    red[tid] = e; __syncthreads();
    for (int o = 64; o; o >>= 1) { if (tid < o) red[tid] += red[tid + o]; __syncthreads(); }
    float inv = 1.f / red[0];
    p_s[tid] = e * inv;
    __syncthreads();
    const float* fb = hopfeat + (size_t)(b * N_) * ST;
    int h = tid * 4;
    float4 acc = {0.f, 0.f, 0.f, 0.f};
#pragma unroll 4
    for (int n = 0; n < N_; n++) {
        float p = p_s[n];
        float4 f = *(const float4*)(fb + (size_t)n * ST + h);
        acc.x += p * f.x; acc.y += p * f.y; acc.z += p * f.z; acc.w += p * f.w;
    }
    *(float4*)&g_query2[(size_t)bt * H_ + h] = acc;
}

// ---------------- launch ----------------
static float* sym(const void* s) {
    void* p = nullptr;
    cudaGetSymbolAddress(&p, s);
    return (float*)p;
}

extern "C" void kernel_launch(void* const* d_in, const int* in_sizes, int n_in,
                              void* d_out, int out_size) {
    const float* attn_mem = (const float*)d_in[0];
    const int*   mem_sizes= (const int*)  d_in[1];
    const float* lstm_in  = (const float*)d_in[2];
    const float* init_h   = (const float*)d_in[3];
    const float* init_c   = (const float*)d_in[4];
    const float* init_i   = (const float*)d_in[5];
    const float* w_ih     = (const float*)d_in[6];
    const float* w_hh     = (const float*)d_in[7];
    const float* b_ih     = (const float*)d_in[8];
    const float* b_hh     = (const float*)d_in[9];
    const float* attn_wm  = (const float*)d_in[10];
    const float* attn_wq  = (const float*)d_in[11];
    const float* attn_v   = (const float*)d_in[12];
    const float* hop_wm   = (const float*)d_in[13];
    const float* hop_wq   = (const float*)d_in[14];
    const float* hop_v    = (const float*)d_in[15];
    float* out = (float*)d_out;

    float* p_feat   = sym(g_feat);
    float* p_wfeat  = sym(g_wfeat);
    float* p_wiht   = sym(g_wiht);
    float* p_bias   = sym(g_bias);
    float* p_X      = sym(g_X);
    float* p_xg     = sym(g_xg);
    float* p_query  = sym(g_query);
    float* p_qw     = sym(g_qw);
    float* p_score  = sym(g_score);
    float* p_query2 = sym(g_query2);
    float* p_qw2    = sym(g_qw2);

    cudaFuncSetAttribute(lstm_persist_kernel,
                         cudaFuncAttributeMaxDynamicSharedMemorySize, 512 * 16 * 4);

    // prep
    pack_kernel   <<<(D_*G4 + 255)/256, 256>>>(w_ih, w_hh, b_ih, b_hh, attn_wm, hop_wm);
    build_x_kernel<<<(B_*TQ*D_ + 255)/256, 256>>>(lstm_in, init_i);
    init_h_kernel <<<(B_*H_ + 255)/256, 256>>>(init_h);

    // merged feature GEMM: [4096,512] @ [512,1024] -> g_feat (attn|hop)
    sgemm64<<<dim3(FEATW/64, (B_*N_)/64), 256>>>(attn_mem, p_wfeat, p_feat, nullptr, B_*N_, FEATW, D_);

    // input gates: [1024,512] @ [512,2048] + bias
    sgemm64<<<dim3(G4/64, (B_*TQ)/64), 256>>>(p_X, p_wiht, p_xg, p_bias, B_*TQ, G4, D_);

    // LSTM recurrence: one persistent launch with L2-native barrier
    lstm_persist_kernel<<<128, 256, 512*16*4>>>(init_c);

    // hop attention (hop feat = cols 512..1023 of g_feat)
    sgemm64<<<dim3(H_/64, (B_*TQ)/64), 256>>>(p_query, hop_wq, p_qw, nullptr, B_*TQ, H_, H_);
    score_kernel<<<B_*TQ, 256>>>(p_feat + 512, FEATW, p_qw, hop_v, p_score);
    softmax_wsum_kernel<<<B_*TQ, 128>>>(mem_sizes, p_feat + 512, FEATW);

    // final score (attn feat = cols 0..511)
    sgemm64<<<dim3(H_/64, (B_*TQ)/64), 256>>>(p_query2, attn_wq, p_qw2, nullptr, B_*TQ, H_, H_);
    score_kernel<<<B_*TQ, 256>>>(p_feat, FEATW, p_qw2, attn_v, out);
}

// round 15
// speedup vs baseline: 1.5618x; 1.1040x over previous
#include <cuda_runtime.h>
#include <cstddef>

#define B_  32
#define N_  128
#define D_  512
#define H_  512
#define T_  31
#define TQ  32
#define G4  2048   // 4*H
#define FEATW 1024 // attn|hop feature cols

// ---------------- device scratch ----------------
__device__ float g_feat [B_*N_*FEATW];    // [B*N][1024]: cols 0..511 attn, 512..1023 hop
__device__ float g_wfeat[D_*FEATW];       // [k][1024] = attn_wm | hop_wm
__device__ float g_wiht[D_*G4];           // packed: [k][j*4+g] = w_ih[g*H+j][k]
__device__ float g_whh [H_*G4];           // packed: [k][j*4+g] = w_hh[g*H+j][k]
__device__ float g_bias[G4];              // packed b_ih+b_hh
__device__ float g_X   [B_*TQ*D_];        // lstm input incl. init_i row
__device__ float g_xg  [B_*TQ*G4];        // X @ w_ih^T + bias (packed cols)
__device__ float g_hT  [2][H_*B_];        // transposed h state: [k][b], double-buffered
__device__ float g_query [B_*TQ*H_];
__device__ float g_qw    [B_*TQ*H_];
__device__ float g_score [B_*TQ*N_];
__device__ float g_query2[B_*TQ*H_];
__device__ float g_qw2   [B_*TQ*H_];
__device__ unsigned g_bar;

__device__ __forceinline__ float tanh_fast(float x) {
    float y; asm("tanh.approx.f32 %0, %1;" : "=f"(y) : "f"(x)); return y;
}
__device__ __forceinline__ float sigmoid_f(float x) {
    return 1.f / (1.f + __expf(-x));
}

// ---------------- weight pack / transpose (R3, passed) ----------------
__global__ void pack_kernel(const float* __restrict__ w_ih, const float* __restrict__ w_hh,
                            const float* __restrict__ b_ih, const float* __restrict__ b_hh,
                            const float* __restrict__ attn_wm, const float* __restrict__ hop_wm) {
    int idx = blockIdx.x * blockDim.x + threadIdx.x;
    if (idx < D_ * G4) {
        int k = idx >> 11, col = idx & 2047;
        int j = col >> 2, g = col & 3;
        int row = g * H_ + j;
        g_wiht[idx] = w_ih[row * D_ + k];
        g_whh [idx] = w_hh[row * H_ + k];
        if (idx < G4) g_bias[idx] = b_ih[row] + b_hh[row];
    }
    if (idx < D_ * FEATW) {
        int k = idx >> 10, c = idx & 1023;
        g_wfeat[idx] = (c < 512) ? attn_wm[k * H_ + c] : hop_wm[k * H_ + (c - 512)];
    }
}

__global__ void build_x_kernel(const float* __restrict__ lstm_in, const float* __restrict__ init_i) {
    int idx = blockIdx.x * blockDim.x + threadIdx.x;
    if (idx >= B_ * TQ * D_) return;
    int d  = idx & (D_ - 1);
    int bt = idx >> 9;
    int t = bt & 31, b = bt >> 5;
    g_X[idx] = (t == 0) ? init_i[d] : lstm_in[(b * T_ + (t - 1)) * D_ + d];
}

__global__ void init_h_kernel(const float* __restrict__ init_h) {
    int idx = blockIdx.x * blockDim.x + threadIdx.x;
    if (idx == 0) g_bar = 0u;
    if (idx >= B_ * H_) return;
    int j = idx >> 5;                     // idx = j*32 + b
    g_hT[0][idx] = init_h[j];
}

// ---------------- tiled fp32 GEMM 64x64 (R1-proven; small GEMMs) ----------------
__global__ void sgemm64(const float* __restrict__ A, const float* __restrict__ Bm,
                        float* __restrict__ C, const float* __restrict__ bias,
                        int M, int N, int K) {
    __shared__ __align__(16) float As[16][64];   // [k][m]
    __shared__ __align__(16) float Bs[16][64];   // [k][n]
    const int bm = blockIdx.y * 64, bn = blockIdx.x * 64;
    const int tid = threadIdx.x;
    const int tn = tid & 15, tm = tid >> 4;
    const int arow = tid >> 2,  acol = (tid & 3) << 2;
    const int brow = tid >> 4,  bcol = (tid & 15) << 2;
    float acc[4][4] = {};
    for (int k0 = 0; k0 < K; k0 += 16) {
        float4 a4 = *(const float4*)(A  + (size_t)(bm + arow) * K + k0 + acol);
        float4 b4 = *(const float4*)(Bm + (size_t)(k0 + brow) * N + bn + bcol);
        As[acol + 0][arow] = a4.x;
        As[acol + 1][arow] = a4.y;
        As[acol + 2][arow] = a4.z;
        As[acol + 3][arow] = a4.w;
        *(float4*)&Bs[brow][bcol] = b4;
        __syncthreads();
#pragma unroll
        for (int k = 0; k < 16; k++) {
            float4 av = *(const float4*)&As[k][tm << 2];
            float4 bv = *(const float4*)&Bs[k][tn << 2];
            float a_[4] = {av.x, av.y, av.z, av.w};
            float b_[4] = {bv.x, bv.y, bv.z, bv.w};
#pragma unroll
            for (int i = 0; i < 4; i++)
#pragma unroll
                for (int j = 0; j < 4; j++) acc[i][j] += a_[i] * b_[j];
        }
        __syncthreads();
    }
#pragma unroll
    for (int i = 0; i < 4; i++) {
        int row = bm + (tm << 2) + i;
#pragma unroll
        for (int j = 0; j < 4; j++) {
            int col = bn + (tn << 2) + j;
            float v = acc[i][j];
            if (bias) v += bias[col];
            C[(size_t)row * N + col] = v;
        }
    }
}

// ---------------- tiled fp32 GEMM 128x128, 8x8 microtile, double-buffered ----------------
// 256 threads = 16(tx) x 16(ty); thread owns rows {ty*4..+3, 64+ty*4..+3},
// cols {tx*4..+3, 64+tx*4..+3}. BK=8; one __syncthreads per chunk.
__global__ void __launch_bounds__(256) sgemm128(const float* __restrict__ A,
                                                const float* __restrict__ Bm,
                                                float* __restrict__ C,
                                                const float* __restrict__ bias,
                                                int M, int N, int K) {
    __shared__ __align__(16) float As[2][8][132];   // [buf][k][m]
    __shared__ __align__(16) float Bs[2][8][132];   // [buf][k][n]
    const int bm = blockIdx.y * 128, bn = blockIdx.x * 128;
    const int tid = threadIdx.x;
    const int tx = tid & 15, ty = tid >> 4;
    const int ar = tid >> 1, ak = (tid & 1) << 2;   // A: row 0..127, k 0 or 4
    const int br = tid >> 5, bc = (tid & 31) << 2;  // B: k-row 0..7, col 0..124

    float4 pa = *(const float4*)(A  + (size_t)(bm + ar) * K + ak);
    float4 pb = *(const float4*)(Bm + (size_t)br * N + bn + bc);
    As[0][ak + 0][ar] = pa.x;
    As[0][ak + 1][ar] = pa.y;
    As[0][ak + 2][ar] = pa.z;
    As[0][ak + 3][ar] = pa.w;
    *(float4*)&Bs[0][br][bc] = pb;
    __syncthreads();

    float acc[8][8] = {};
    const int NCHK = K >> 3;
    for (int kc = 0; kc < NCHK; kc++) {
        const int buf = kc & 1;
        if (kc + 1 < NCHK) {
            int k0 = (kc + 1) << 3;
            pa = *(const float4*)(A  + (size_t)(bm + ar) * K + k0 + ak);
            pb = *(const float4*)(Bm + (size_t)(k0 + br) * N + bn + bc);
        }
#pragma unroll
        for (int k = 0; k < 8; k++) {
            float4 a0 = *(const float4*)&As[buf][k][ty << 2];
            float4 a1 = *(const float4*)&As[buf][k][64 + (ty << 2)];
            float4 b0 = *(const float4*)&Bs[buf][k][tx << 2];
            float4 b1 = *(const float4*)&Bs[buf][k][64 + (tx << 2)];
            float a_[8] = {a0.x, a0.y, a0.z, a0.w, a1.x, a1.y, a1.z, a1.w};
            float b_[8] = {b0.x, b0.y, b0.z, b0.w, b1.x, b1.y, b1.z, b1.w};
#pragma unroll
            for (int i = 0; i < 8; i++)
#pragma unroll
                for (int j = 0; j < 8; j++) acc[i][j] += a_[i] * b_[j];
        }
        if (kc + 1 < NCHK) {
            const int nb = buf ^ 1;
            As[nb][ak + 0][ar] = pa.x;
            As[nb][ak + 1][ar] = pa.y;
            As[nb][ak + 2][ar] = pa.z;
            As[nb][ak + 3][ar] = pa.w;
            *(float4*)&Bs[nb][br][bc] = pb;
            __syncthreads();
        }
    }

#pragma unroll
    for (int ib = 0; ib < 2; ib++) {
#pragma unroll
        for (int i = 0; i < 4; i++) {
            int row = bm + ib * 64 + (ty << 2) + i;
#pragma unroll
            for (int jb = 0; jb < 2; jb++) {
                int col = bn + jb * 64 + (tx << 2);
                float4 v;
                v.x = acc[ib * 4 + i][jb * 4 + 0];
                v.y = acc[ib * 4 + i][jb * 4 + 1];
                v.z = acc[ib * 4 + i][jb * 4 + 2];
                v.w = acc[ib * 4 + i][jb * 4 + 3];
                if (bias) {
                    v.x += bias[col + 0];
                    v.y += bias[col + 1];
                    v.z += bias[col + 2];
                    v.w += bias[col + 3];
                }
                *(float4*)(C + (size_t)row * N + col) = v;
            }
        }
    }
}

// ---------------- persistent LSTM with L2-native release/acquire barrier (R12, passed) ----------------
__global__ void __launch_bounds__(256, 1) lstm_persist_kernel(const float* __restrict__ init_c) {
    extern __shared__ float ws[];            // [512][16]  32KB dynamic
    __shared__ float red[8][32 * 17 + 1];    // [ks][b*17 + c]
    __shared__ float cst[128];               // c state: [b*4 + jl]
    const int bid = blockIdx.x;
    const int tid = threadIdx.x;
    const int ks = tid >> 5, lane = tid & 31;
    const int bq = lane & 7, cq = lane >> 3;

    {
        const float* src = g_whh + bid * 16;
        for (int i = tid; i < 512 * 4; i += 256) {   // 2048 float4s
            int k = i >> 2, cc = (i & 3) << 2;
            *(float4*)&ws[k * 16 + cc] = *(const float4*)(src + (size_t)k * G4 + cc);
        }
    }
    if (tid < 128) cst[tid] = init_c[bid * 4 + (tid & 3)];
    __syncthreads();

    const float* __restrict__ wp = ws + (ks << 6) * 16 + (cq << 2);

    for (int t = 0; t < TQ; t++) {
        const float* __restrict__ hp = g_hT[t & 1] + (ks << 6) * B_ + (bq << 2);
        float acc[4][4] = {};
#pragma unroll 8
        for (int k = 0; k < 64; k++) {
            float4 h4 = __ldcg((const float4*)(hp + k * B_));   // L2-coherent read
            float4 w4 = *(const float4*)(wp + k * 16);
            float h_[4] = {h4.x, h4.y, h4.z, h4.w};
            float w_[4] = {w4.x, w4.y, w4.z, w4.w};
#pragma unroll
            for (int i = 0; i < 4; i++)
#pragma unroll
                for (int j = 0; j < 4; j++) acc[i][j] += h_[i] * w_[j];
        }
#pragma unroll
        for (int i = 0; i < 4; i++)
#pragma unroll
            for (int j = 0; j < 4; j++)
                red[ks][((bq << 2) + i) * 17 + (cq << 2) + j] = acc[i][j];
        __syncthreads();

        if (tid < 128) {
            int b = tid >> 2, jl = tid & 3;
            int j = (bid << 2) + jl;
            int bt = b * TQ + t;
            const float* xg = g_xg + (size_t)bt * G4 + bid * 16 + (jl << 2);
            float gate[4];
#pragma unroll
            for (int g = 0; g < 4; g++) {
                int c = (jl << 2) + g;
                float s = 0.f;
#pragma unroll
                for (int kk = 0; kk < 8; kk++) s += red[kk][b * 17 + c];
                gate[g] = s + xg[g];
            }
            float c_ = sigmoid_f(gate[1]) * cst[tid] + sigmoid_f(gate[0]) * tanh_fast(gate[2]);
            float h_ = sigmoid_f(gate[3]) * tanh_fast(c_);
            cst[tid] = c_;
            __stcg(&g_hT[(t & 1) ^ 1][j * B_ + b], h_);         // L2-coherent write
            __stcg(&g_query[(size_t)bt * H_ + j], h_);
        }
        __syncthreads();                        // red WAR + orders h stores before release
        if (t != TQ - 1) {
            if (tid == 0) {
                asm volatile("red.release.gpu.global.add.u32 [%0], 1;"
                             :: "l"(&g_bar) : "memory");
                unsigned target = 128u * (unsigned)(t + 1);
                unsigned v;
                do {
                    asm volatile("ld.acquire.gpu.global.u32 %0, [%1];"
                                 : "=r"(v) : "l"(&g_bar) : "memory");
                } while (v < target);
            }
            __syncthreads();                    // broadcast acquire to all threads
        }
    }
}

// ---------------- attention score (R3, passed) ----------------
__global__ void score_kernel(const float* __restrict__ feat, int ST,
                             const float* __restrict__ qw,
                             const float* __restrict__ v, float* __restrict__ out) {
    __shared__ __align__(16) float q_s[H_];
    __shared__ __align__(16) float v_s[H_];
    int bt = blockIdx.x;                 // 1024 blocks
    int b  = bt >> 5;
    int tid = threadIdx.x;               // 256
    q_s[tid]       = qw[(size_t)bt * H_ + tid];
    q_s[tid + 256] = qw[(size_t)bt * H_ + tid + 256];
    v_s[tid]       = v[tid];
    v_s[tid + 256] = v[tid + 256];
    __syncthreads();
    int warp = tid >> 5, lane = tid & 31;
    const float* fb = feat + (size_t)(b * N_) * ST;
    for (int n = warp; n < N_; n += 8) {
        const float* fr = fb + (size_t)n * ST;
        float acc = 0.f;
#pragma unroll
        for (int c = 0; c < 4; c++) {
            int h = c * 128 + lane * 4;
            float4 f4 = *(const float4*)(fr + h);
            float4 q4 = *(const float4*)(q_s + h);
            float4 v4 = *(const float4*)(v_s + h);
            acc += tanh_fast(f4.x + q4.x) * v4.x;
            acc += tanh_fast(f4.y + q4.y) * v4.y;
            acc += tanh_fast(f4.z + q4.z) * v4.z;
            acc += tanh_fast(f4.w + q4.w) * v4.w;
        }
#pragma unroll
        for (int s = 16; s; s >>= 1) acc += __shfl_xor_sync(0xffffffffu, acc, s);
        if (lane == 0) out[(size_t)bt * N_ + n] = acc;
    }
}

// ---------------- masked softmax + weighted sum (R3, passed) ----------------
__global__ void softmax_wsum_kernel(const int* __restrict__ mem_sizes,
                                    const float* __restrict__ hopfeat, int ST) {
    __shared__ float p_s[N_];
    __shared__ float red[128];
    int bt = blockIdx.x, b = bt >> 5;
    int tid = threadIdx.x;               // 128
    int ms = mem_sizes[b];
    float s = g_score[bt * N_ + tid];
    s = (tid < ms) ? s : -1e30f;
    red[tid] = s; __syncthreads();
    for (int o = 64; o; o >>= 1) { if (tid < o) red[tid] = fmaxf(red[tid], red[tid + o]); __syncthreads(); }
    float mx = red[0]; __syncthreads();
    float e = __expf(s - mx);
    red[tid] = e; __syncthreads();
    for (int o = 64; o; o >>= 1) { if (tid < o) red[tid] += red[tid + o]; __syncthreads(); }
    float inv = 1.f / red[0];
    p_s[tid] = e * inv;
    __syncthreads();
    const float* fb = hopfeat + (size_t)(b * N_) * ST;
    int h = tid * 4;
    float4 acc = {0.f, 0.f, 0.f, 0.f};
#pragma unroll 4
    for (int n = 0; n < N_; n++) {
        float p = p_s[n];
        float4 f = *(const float4*)(fb + (size_t)n * ST + h);
        acc.x += p * f.x; acc.y += p * f.y; acc.z += p * f.z; acc.w += p * f.w;
    }
    *(float4*)&g_query2[(size_t)bt * H_ + h] = acc;
}

// ---------------- launch ----------------
static float* sym(const void* s) {
    void* p = nullptr;
    cudaGetSymbolAddress(&p, s);
    return (float*)p;
}

extern "C" void kernel_launch(void* const* d_in, const int* in_sizes, int n_in,
                              void* d_out, int out_size) {
    const float* attn_mem = (const float*)d_in[0];
    const int*   mem_sizes= (const int*)  d_in[1];
    const float* lstm_in  = (const float*)d_in[2];
    const float* init_h   = (const float*)d_in[3];
    const float* init_c   = (const float*)d_in[4];
    const float* init_i   = (const float*)d_in[5];
    const float* w_ih     = (const float*)d_in[6];
    const float* w_hh     = (const float*)d_in[7];
    const float* b_ih     = (const float*)d_in[8];
    const float* b_hh     = (const float*)d_in[9];
    const float* attn_wm  = (const float*)d_in[10];
    const float* attn_wq  = (const float*)d_in[11];
    const float* attn_v   = (const float*)d_in[12];
    const float* hop_wm   = (const float*)d_in[13];
    const float* hop_wq   = (const float*)d_in[14];
    const float* hop_v    = (const float*)d_in[15];
    float* out = (float*)d_out;

    float* p_feat   = sym(g_feat);
    float* p_wfeat  = sym(g_wfeat);
    float* p_wiht   = sym(g_wiht);
    float* p_bias   = sym(g_bias);
    float* p_X      = sym(g_X);
    float* p_xg     = sym(g_xg);
    float* p_query  = sym(g_query);
    float* p_qw     = sym(g_qw);
    float* p_score  = sym(g_score);
    float* p_query2 = sym(g_query2);
    float* p_qw2    = sym(g_qw2);

    cudaFuncSetAttribute(lstm_persist_kernel,
                         cudaFuncAttributeMaxDynamicSharedMemorySize, 512 * 16 * 4);

    // prep
    pack_kernel   <<<(D_*G4 + 255)/256, 256>>>(w_ih, w_hh, b_ih, b_hh, attn_wm, hop_wm);
    build_x_kernel<<<(B_*TQ*D_ + 255)/256, 256>>>(lstm_in, init_i);
    init_h_kernel <<<(B_*H_ + 255)/256, 256>>>(init_h);

    // merged feature GEMM: [4096,512] @ [512,1024] -> g_feat (attn|hop)
    sgemm128<<<dim3(FEATW/128, (B_*N_)/128), 256>>>(attn_mem, p_wfeat, p_feat, nullptr, B_*N_, FEATW, D_);

    // input gates: [1024,512] @ [512,2048] + bias
    sgemm128<<<dim3(G4/128, (B_*TQ)/128), 256>>>(p_X, p_wiht, p_xg, p_bias, B_*TQ, G4, D_);

    // LSTM recurrence: one persistent launch with L2-native barrier
    lstm_persist_kernel<<<128, 256, 512*16*4>>>(init_c);

    // hop attention (hop feat = cols 512..1023 of g_feat)
    sgemm64<<<dim3(H_/64, (B_*TQ)/64), 256>>>(p_query, hop_wq, p_qw, nullptr, B_*TQ, H_, H_);
    score_kernel<<<B_*TQ, 256>>>(p_feat + 512, FEATW, p_qw, hop_v, p_score);
    softmax_wsum_kernel<<<B_*TQ, 128>>>(mem_sizes, p_feat + 512, FEATW);

    // final score (attn feat = cols 0..511)
    sgemm64<<<dim3(H_/64, (B_*TQ)/64), 256>>>(p_query2, attn_wq, p_qw2, nullptr, B_*TQ, H_, H_);
    score_kernel<<<B_*TQ, 256>>>(p_feat, FEATW, p_qw2, attn_v, out);
}

// round 16
// speedup vs baseline: 1.7032x; 1.0905x over previous
#include <cuda_runtime.h>
#include <cstddef>

#define B_  32
#define N_  128
#define D_  512
#define H_  512
#define T_  31
#define TQ  32
#define G4  2048   // 4*H
#define FEATW 1024 // attn|hop feature cols

// ---------------- device scratch ----------------
__device__ float g_feat [B_*N_*FEATW];    // [B*N][1024]: cols 0..511 attn, 512..1023 hop
__device__ float g_wfeat[D_*FEATW];       // [k][1024] = attn_wm | hop_wm
__device__ float g_wiht[D_*G4];           // packed: [k][j*4+g] = w_ih[g*H+j][k]
__device__ float g_whh [H_*G4];           // packed: [k][j*4+g] = w_hh[g*H+j][k]
__device__ float g_bias[G4];              // packed b_ih+b_hh
__device__ float g_X   [B_*TQ*D_];        // lstm input incl. init_i row
__device__ float g_xg  [B_*TQ*G4];        // X @ w_ih^T + bias (packed cols)
__device__ float g_hT  [2][H_*B_];        // transposed h state: [k][b], double-buffered
__device__ float g_query [B_*TQ*H_];
__device__ float g_qw    [B_*TQ*H_];
__device__ float g_score [B_*TQ*N_];
__device__ float g_query2[B_*TQ*H_];
__device__ float g_qw2   [B_*TQ*H_];
__device__ unsigned g_bar;

__device__ __forceinline__ float tanh_fast(float x) {
    float y; asm("tanh.approx.f32 %0, %1;" : "=f"(y) : "f"(x)); return y;
}
__device__ __forceinline__ float sigmoid_f(float x) {
    return 1.f / (1.f + __expf(-x));
}

// ---------------- pack: wfeat + bias (already coalesced) ----------------
__global__ void pack_kernel(const float* __restrict__ b_ih, const float* __restrict__ b_hh,
                            const float* __restrict__ attn_wm, const float* __restrict__ hop_wm) {
    int idx = blockIdx.x * blockDim.x + threadIdx.x;
    if (idx < G4) {
        int j = idx >> 2, g = idx & 3;
        int row = g * H_ + j;
        g_bias[idx] = b_ih[row] + b_hh[row];
    }
    if (idx < D_ * FEATW) {
        int k = idx >> 10, c = idx & 1023;
        g_wfeat[idx] = (c < 512) ? attn_wm[k * H_ + c] : hop_wm[k * H_ + (c - 512)];
    }
}

// ---------------- pack: coalesced transpose for w_ih / w_hh ----------------
// g_wiht[k][col] = w_ih[rowof(col)][k], rowof(col) = (col&3)*512 + (col>>2).
// 32x32 smem tiles: reads coalesced in k, writes coalesced in col.
__global__ void pack_tr_kernel(const float* __restrict__ w_ih, const float* __restrict__ w_hh) {
    __shared__ float t0[32][33];
    __shared__ float t1[32][33];
    const int kb = blockIdx.x * 32, cb = blockIdx.y * 32;
    const int lk = threadIdx.x & 31, lr = threadIdx.x >> 5;   // 8 rows per pass
#pragma unroll
    for (int rr = 0; rr < 4; rr++) {
        int ci = rr * 8 + lr;                 // col-in-tile
        int col = cb + ci;
        int row = (col & 3) * H_ + (col >> 2);
        t0[ci][lk] = w_ih[(size_t)row * D_ + kb + lk];
        t1[ci][lk] = w_hh[(size_t)row * H_ + kb + lk];
    }
    __syncthreads();
#pragma unroll
    for (int rr = 0; rr < 4; rr++) {
        int ki = rr * 8 + lr;
        g_wiht[(size_t)(kb + ki) * G4 + cb + lk] = t0[lk][ki];
        g_whh [(size_t)(kb + ki) * G4 + cb + lk] = t1[lk][ki];
    }
}

__global__ void build_x_kernel(const float* __restrict__ lstm_in, const float* __restrict__ init_i) {
    int idx = blockIdx.x * blockDim.x + threadIdx.x;
    if (idx >= B_ * TQ * D_) return;
    int d  = idx & (D_ - 1);
    int bt = idx >> 9;
    int t = bt & 31, b = bt >> 5;
    g_X[idx] = (t == 0) ? init_i[d] : lstm_in[(b * T_ + (t - 1)) * D_ + d];
}

__global__ void init_h_kernel(const float* __restrict__ init_h) {
    int idx = blockIdx.x * blockDim.x + threadIdx.x;
    if (idx == 0) g_bar = 0u;
    if (idx >= B_ * H_) return;
    int j = idx >> 5;                     // idx = j*32 + b
    g_hT[0][idx] = init_h[j];
}

// ---------------- tiled fp32 GEMM 64x64 (R1-proven; small GEMMs) ----------------
__global__ void sgemm64(const float* __restrict__ A, const float* __restrict__ Bm,
                        float* __restrict__ C, const float* __restrict__ bias,
                        int M, int N, int K) {
    __shared__ __align__(16) float As[16][64];   // [k][m]
    __shared__ __align__(16) float Bs[16][64];   // [k][n]
    const int bm = blockIdx.y * 64, bn = blockIdx.x * 64;
    const int tid = threadIdx.x;
    const int tn = tid & 15, tm = tid >> 4;
    const int arow = tid >> 2,  acol = (tid & 3) << 2;
    const int brow = tid >> 4,  bcol = (tid & 15) << 2;
    float acc[4][4] = {};
    for (int k0 = 0; k0 < K; k0 += 16) {
        float4 a4 = *(const float4*)(A  + (size_t)(bm + arow) * K + k0 + acol);
        float4 b4 = *(const float4*)(Bm + (size_t)(k0 + brow) * N + bn + bcol);
        As[acol + 0][arow] = a4.x;
        As[acol + 1][arow] = a4.y;
        As[acol + 2][arow] = a4.z;
        As[acol + 3][arow] = a4.w;
        *(float4*)&Bs[brow][bcol] = b4;
        __syncthreads();
#pragma unroll
        for (int k = 0; k < 16; k++) {
            float4 av = *(const float4*)&As[k][tm << 2];
            float4 bv = *(const float4*)&Bs[k][tn << 2];
            float a_[4] = {av.x, av.y, av.z, av.w};
            float b_[4] = {bv.x, bv.y, bv.z, bv.w};
#pragma unroll
            for (int i = 0; i < 4; i++)
#pragma unroll
                for (int j = 0; j < 4; j++) acc[i][j] += a_[i] * b_[j];
        }
        __syncthreads();
    }
#pragma unroll
    for (int i = 0; i < 4; i++) {
        int row = bm + (tm << 2) + i;
#pragma unroll
        for (int j = 0; j < 4; j++) {
            int col = bn + (tn << 2) + j;
            float v = acc[i][j];
            if (bias) v += bias[col];
            C[(size_t)row * N + col] = v;
        }
    }
}

// ---------------- tiled fp32 GEMM 128x128, 8x8 microtile, double-buffered (R13, passed) ----------------
__global__ void __launch_bounds__(256) sgemm128(const float* __restrict__ A,
                                                const float* __restrict__ Bm,
                                                float* __restrict__ C,
                                                const float* __restrict__ bias,
                                                int M, int N, int K) {
    __shared__ __align__(16) float As[2][8][132];   // [buf][k][m]
    __shared__ __align__(16) float Bs[2][8][132];   // [buf][k][n]
    const int bm = blockIdx.y * 128, bn = blockIdx.x * 128;
    const int tid = threadIdx.x;
    const int tx = tid & 15, ty = tid >> 4;
    const int ar = tid >> 1, ak = (tid & 1) << 2;   // A: row 0..127, k 0 or 4
    const int br = tid >> 5, bc = (tid & 31) << 2;  // B: k-row 0..7, col 0..124

    float4 pa = *(const float4*)(A  + (size_t)(bm + ar) * K + ak);
    float4 pb = *(const float4*)(Bm + (size_t)br * N + bn + bc);
    As[0][ak + 0][ar] = pa.x;
    As[0][ak + 1][ar] = pa.y;
    As[0][ak + 2][ar] = pa.z;
    As[0][ak + 3][ar] = pa.w;
    *(float4*)&Bs[0][br][bc] = pb;
    __syncthreads();

    float acc[8][8] = {};
    const int NCHK = K >> 3;
    for (int kc = 0; kc < NCHK; kc++) {
        const int buf = kc & 1;
        if (kc + 1 < NCHK) {
            int k0 = (kc + 1) << 3;
            pa = *(const float4*)(A  + (size_t)(bm + ar) * K + k0 + ak);
            pb = *(const float4*)(Bm + (size_t)(k0 + br) * N + bn + bc);
        }
#pragma unroll
        for (int k = 0; k < 8; k++) {
            float4 a0 = *(const float4*)&As[buf][k][ty << 2];
            float4 a1 = *(const float4*)&As[buf][k][64 + (ty << 2)];
            float4 b0 = *(const float4*)&Bs[buf][k][tx << 2];
            float4 b1 = *(const float4*)&Bs[buf][k][64 + (tx << 2)];
            float a_[8] = {a0.x, a0.y, a0.z, a0.w, a1.x, a1.y, a1.z, a1.w};
            float b_[8] = {b0.x, b0.y, b0.z, b0.w, b1.x, b1.y, b1.z, b1.w};
#pragma unroll
            for (int i = 0; i < 8; i++)
#pragma unroll
                for (int j = 0; j < 8; j++) acc[i][j] += a_[i] * b_[j];
        }
        if (kc + 1 < NCHK) {
            const int nb = buf ^ 1;
            As[nb][ak + 0][ar] = pa.x;
            As[nb][ak + 1][ar] = pa.y;
            As[nb][ak + 2][ar] = pa.z;
            As[nb][ak + 3][ar] = pa.w;
            *(float4*)&Bs[nb][br][bc] = pb;
            __syncthreads();
        }
    }

#pragma unroll
    for (int ib = 0; ib < 2; ib++) {
#pragma unroll
        for (int i = 0; i < 4; i++) {
            int row = bm + ib * 64 + (ty << 2) + i;
#pragma unroll
            for (int jb = 0; jb < 2; jb++) {
                int col = bn + jb * 64 + (tx << 2);
                float4 v;
                v.x = acc[ib * 4 + i][jb * 4 + 0];
                v.y = acc[ib * 4 + i][jb * 4 + 1];
                v.z = acc[ib * 4 + i][jb * 4 + 2];
                v.w = acc[ib * 4 + i][jb * 4 + 3];
                if (bias) {
                    v.x += bias[col + 0];
                    v.y += bias[col + 1];
                    v.z += bias[col + 2];
                    v.w += bias[col + 3];
                }
                *(float4*)(C + (size_t)row * N + col) = v;
            }
        }
    }
}

// ---------------- persistent LSTM: L2 barrier + 16-deep h prefetch pipeline ----------------
__global__ void __launch_bounds__(256, 1) lstm_persist_kernel(const float* __restrict__ init_c) {
    extern __shared__ float ws[];            // [512][16]  32KB dynamic
    __shared__ float red[8][32 * 17 + 1];    // [ks][b*17 + c]
    __shared__ float cst[128];               // c state: [b*4 + jl]
    const int bid = blockIdx.x;
    const int tid = threadIdx.x;
    const int ks = tid >> 5, lane = tid & 31;
    const int bq = lane & 7, cq = lane >> 3;

    {
        const float* src = g_whh + bid * 16;
        for (int i = tid; i < 512 * 4; i += 256) {   // 2048 float4s
            int k = i >> 2, cc = (i & 3) << 2;
            *(float4*)&ws[k * 16 + cc] = *(const float4*)(src + (size_t)k * G4 + cc);
        }
    }
    if (tid < 128) cst[tid] = init_c[bid * 4 + (tid & 3)];
    __syncthreads();

    const float* __restrict__ wp = ws + (ks << 6) * 16 + (cq << 2);
    const int gb = tid >> 2, gjl = tid & 3;                  // gate-phase coords
    const float* __restrict__ xgp = g_xg + (size_t)(gb * TQ) * G4 + bid * 16 + (gjl << 2);

    for (int t = 0; t < TQ; t++) {
        const float* __restrict__ hp = g_hT[t & 1] + (ks << 6) * B_ + (bq << 2);

        // hoist xg load (independent of the dot product) to overlap its L2 latency
        float4 xg4 = make_float4(0.f, 0.f, 0.f, 0.f);
        if (tid < 128) xg4 = *(const float4*)(xgp + (size_t)t * G4);

        float acc[4][4] = {};
        // 16-deep h prefetch pipeline: MLP=16 on the L2-coherent loads
        float4 hbuf[16];
#pragma unroll
        for (int i = 0; i < 16; i++) hbuf[i] = __ldcg((const float4*)(hp + i * B_));
#pragma unroll
        for (int kk = 0; kk < 4; kk++) {
#pragma unroll
            for (int i = 0; i < 16; i++) {
                float4 h4 = hbuf[i];
                if (kk < 3) hbuf[i] = __ldcg((const float4*)(hp + ((kk + 1) * 16 + i) * B_));
                int k = kk * 16 + i;
                float4 w4 = *(const float4*)(wp + k * 16);
                float h_[4] = {h4.x, h4.y, h4.z, h4.w};
                float w_[4] = {w4.x, w4.y, w4.z, w4.w};
#pragma unroll
                for (int ii = 0; ii < 4; ii++)
#pragma unroll
                    for (int jj = 0; jj < 4; jj++) acc[ii][jj] += h_[ii] * w_[jj];
            }
        }
#pragma unroll
        for (int i = 0; i < 4; i++)
#pragma unroll
            for (int j = 0; j < 4; j++)
                red[ks][((bq << 2) + i) * 17 + (cq << 2) + j] = acc[i][j];
        __syncthreads();

        if (tid < 128) {
            int b = gb, jl = gjl;
            int j = (bid << 2) + jl;
            int bt = b * TQ + t;
            float xg_[4] = {xg4.x, xg4.y, xg4.z, xg4.w};
            float gate[4];
#pragma unroll
            for (int g = 0; g < 4; g++) {
                int c = (jl << 2) + g;
                float s = 0.f;
#pragma unroll
                for (int kk = 0; kk < 8; kk++) s += red[kk][b * 17 + c];
                gate[g] = s + xg_[g];
            }
            float c_ = sigmoid_f(gate[1]) * cst[tid] + sigmoid_f(gate[0]) * tanh_fast(gate[2]);
            float h_ = sigmoid_f(gate[3]) * tanh_fast(c_);
            cst[tid] = c_;
            __stcg(&g_hT[(t & 1) ^ 1][j * B_ + b], h_);         // L2-coherent write
            __stcg(&g_query[(size_t)bt * H_ + j], h_);
        }
        __syncthreads();                        // red WAR + orders h stores before release
        if (t != TQ - 1) {
            if (tid == 0) {
                asm volatile("red.release.gpu.global.add.u32 [%0], 1;"
                             :: "l"(&g_bar) : "memory");
                unsigned target = 128u * (unsigned)(t + 1);
                unsigned v;
                do {
                    asm volatile("ld.acquire.gpu.global.u32 %0, [%1];"
                                 : "=r"(v) : "l"(&g_bar) : "memory");
                } while (v < target);
            }
            __syncthreads();                    // broadcast acquire to all threads
        }
    }
}

// ---------------- attention score (R3, passed) ----------------
__global__ void score_kernel(const float* __restrict__ feat, int ST,
                             const float* __restrict__ qw,
                             const float* __restrict__ v, float* __restrict__ out) {
    __shared__ __align__(16) float q_s[H_];
    __shared__ __align__(16) float v_s[H_];
    int bt = blockIdx.x;                 // 1024 blocks
    int b  = bt >> 5;
    int tid = threadIdx.x;               // 256
    q_s[tid]       = qw[(size_t)bt * H_ + tid];
    q_s[tid + 256] = qw[(size_t)bt * H_ + tid + 256];
    v_s[tid]       = v[tid];
    v_s[tid + 256] = v[tid + 256];
    __syncthreads();
    int warp = tid >> 5, lane = tid & 31;
    const float* fb = feat + (size_t)(b * N_) * ST;
    for (int n = warp; n < N_; n += 8) {
        const float* fr = fb + (size_t)n * ST;
        float acc = 0.f;
#pragma unroll
        for (int c = 0; c < 4; c++) {
            int h = c * 128 + lane * 4;
            float4 f4 = *(const float4*)(fr + h);
            float4 q4 = *(const float4*)(q_s + h);
            float4 v4 = *(const float4*)(v_s + h);
            acc += tanh_fast(f4.x + q4.x) * v4.x;
            acc += tanh_fast(f4.y + q4.y) * v4.y;
            acc += tanh_fast(f4.z + q4.z) * v4.z;
            acc += tanh_fast(f4.w + q4.w) * v4.w;
        }
#pragma unroll
        for (int s = 16; s; s >>= 1) acc += __shfl_xor_sync(0xffffffffu, acc, s);
        if (lane == 0) out[(size_t)bt * N_ + n] = acc;
    }
}

// ---------------- masked softmax + weighted sum (R3, passed) ----------------
__global__ void softmax_wsum_kernel(const int* __restrict__ mem_sizes,
                                    const float* __restrict__ hopfeat, int ST) {
    __shared__ float p_s[N_];
    __shared__ float red[128];
    int bt = blockIdx.x, b = bt >> 5;
    int tid = threadIdx.x;               // 128
    int ms = mem_sizes[b];
    float s = g_score[bt * N_ + tid];
    s = (tid < ms) ? s : -1e30f;
    red[tid] = s; __syncthreads();
    for (int o = 64; o; o >>= 1) { if (tid < o) red[tid] = fmaxf(red[tid], red[tid + o]); __syncthreads(); }
    float mx = red[0]; __syncthreads();
    float e = __expf(s - mx);
    red[tid] = e; __syncthreads();
    for (int o = 64; o; o >>= 1) { if (tid < o) red[tid] += red[tid + o]; __syncthreads(); }
    float inv = 1.f / red[0];
    p_s[tid] = e * inv;
    __syncthreads();
    const float* fb = hopfeat + (size_t)(b * N_) * ST;
    int h = tid * 4;
    float4 acc = {0.f, 0.f, 0.f, 0.f};
#pragma unroll 4
    for (int n = 0; n < N_; n++) {
        float p = p_s[n];
        float4 f = *(const float4*)(fb + (size_t)n * ST + h);
        acc.x += p * f.x; acc.y += p * f.y; acc.z += p * f.z; acc.w += p * f.w;
    }
    *(float4*)&g_query2[(size_t)bt * H_ + h] = acc;
}

// ---------------- launch ----------------
static float* sym(const void* s) {
    void* p = nullptr;
    cudaGetSymbolAddress(&p, s);
    return (float*)p;
}

extern "C" void kernel_launch(void* const* d_in, const int* in_sizes, int n_in,
                              void* d_out, int out_size) {
    const float* attn_mem = (const float*)d_in[0];
    const int*   mem_sizes= (const int*)  d_in[1];
    const float* lstm_in  = (const float*)d_in[2];
    const float* init_h   = (const float*)d_in[3];
    const float* init_c   = (const float*)d_in[4];
    const float* init_i   = (const float*)d_in[5];
    const float* w_ih     = (const float*)d_in[6];
    const float* w_hh     = (const float*)d_in[7];
    const float* b_ih     = (const float*)d_in[8];
    const float* b_hh     = (const float*)d_in[9];
    const float* attn_wm  = (const float*)d_in[10];
    const float* attn_wq  = (const float*)d_in[11];
    const float* attn_v   = (const float*)d_in[12];
    const float* hop_wm   = (const float*)d_in[13];
    const float* hop_wq   = (const float*)d_in[14];
    const float* hop_v    = (const float*)d_in[15];
    float* out = (float*)d_out;

    float* p_feat   = sym(g_feat);
    float* p_wfeat  = sym(g_wfeat);
    float* p_wiht   = sym(g_wiht);
    float* p_bias   = sym(g_bias);
    float* p_X      = sym(g_X);
    float* p_xg     = sym(g_xg);
    float* p_query  = sym(g_query);
    float* p_qw     = sym(g_qw);
    float* p_score  = sym(g_score);
    float* p_query2 = sym(g_query2);
    float* p_qw2    = sym(g_qw2);

    cudaFuncSetAttribute(lstm_persist_kernel,
                         cudaFuncAttributeMaxDynamicSharedMemorySize, 512 * 16 * 4);

    // prep
    pack_kernel   <<<(D_*FEATW + 255)/256, 256>>>(b_ih, b_hh, attn_wm, hop_wm);
    pack_tr_kernel<<<dim3(D_/32, G4/32), 256>>>(w_ih, w_hh);
    build_x_kernel<<<(B_*TQ*D_ + 255)/256, 256>>>(lstm_in, init_i);
    init_h_kernel <<<(B_*H_ + 255)/256, 256>>>(init_h);

    // merged feature GEMM: [4096,512] @ [512,1024] -> g_feat (attn|hop)
    sgemm128<<<dim3(FEATW/128, (B_*N_)/128), 256>>>(attn_mem, p_wfeat, p_feat, nullptr, B_*N_, FEATW, D_);

    // input gates: [1024,512] @ [512,2048] + bias
    sgemm128<<<dim3(G4/128, (B_*TQ)/128), 256>>>(p_X, p_wiht, p_xg, p_bias, B_*TQ, G4, D_);

    // LSTM recurrence: one persistent launch with L2-native barrier
    lstm_persist_kernel<<<128, 256, 512*16*4>>>(init_c);

    // hop attention (hop feat = cols 512..1023 of g_feat)
    sgemm64<<<dim3(H_/64, (B_*TQ)/64), 256>>>(p_query, hop_wq, p_qw, nullptr, B_*TQ, H_, H_);
    score_kernel<<<B_*TQ, 256>>>(p_feat + 512, FEATW, p_qw, hop_v, p_score);
    softmax_wsum_kernel<<<B_*TQ, 128>>>(mem_sizes, p_feat + 512, FEATW);

    // final score (attn feat = cols 0..511)
    sgemm64<<<dim3(H_/64, (B_*TQ)/64), 256>>>(p_query2, attn_wq, p_qw2, nullptr, B_*TQ, H_, H_);
    score_kernel<<<B_*TQ, 256>>>(p_feat, FEATW, p_qw2, attn_v, out);
}